// round 10
// baseline (speedup 1.0000x reference)
#include <cuda_runtime.h>
#include <cuda_bf16.h>
#include <cstdint>

// Problem constants
#define BB 512      // batch
#define TT 365      // time steps
#define CC 10       // channels
#define PP 64       // prototypes
#define KK 3650     // T*C
#define KREAL 4015  // 3650 + 365
#define KPAD 4096
#define NKS 128     // K-split chunks (32 deep each)

// Output layout (float32, concatenated in reference return order)
#define O_OUTSEQ 0
#define O_INSEQ  1868800
#define O_DIST   3737600
#define O_IDX    3770368
#define O_LABEL  3770880
#define O_MASK   3771392

// ---------------- scratch (device globals; no allocation allowed) ----------
__device__ float g_Wt[KPAD * PP];           // W^T, k-major: [k][p]  (1 MB)
__device__ float g_part[NKS * BB * PP];     // [ks][b][p] (16.8 MB, L2-resident)
__device__ float g_x2p[BB * NKS];           // x2 partials [b][ks]

// ---------------- packed f32x2 helpers -------------------------------------
__device__ __forceinline__ void fma2(unsigned long long& d,
                                     unsigned long long a,
                                     unsigned long long b) {
    asm("fma.rn.f32x2 %0, %1, %2, %0;" : "+l"(d) : "l"(a), "l"(b));
}
__device__ __forceinline__ unsigned long long pack2(float x) {
    unsigned long long r;
    asm("mov.b64 %0, {%1, %1};" : "=l"(r) : "f"(x));
    return r;
}

// ---------------- prep: buildW tiles + flat pass-through copies -------------
// blocks [0,256): W^T build via 32x32 smem transpose (proven)
// blocks [256,512): flat float4 copies with MLP=8, single pass
#define FLAT_X4   467200               // BB*KK/4
#define FLAT_M4   46720                // BB*TT/4
#define FLAT_TOT  (FLAT_X4 + FLAT_M4)  // 513920
#define NW_BLK    256
#define NC_BLK    256
#define CSTRIDE   (NC_BLK * 256)       // 65536

__global__ void __launch_bounds__(256) k_prep(const float* __restrict__ x,
                                              const float* __restrict__ mask,
                                              const float* __restrict__ proto,
                                              float* __restrict__ out) {
    if (blockIdx.x < NW_BLK) {
        __shared__ float tile[32][33];
        int kt = blockIdx.x & 127;
        int pt = blockIdx.x >> 7;
        int k0 = kt * 32;
        int p0 = pt * 32;
        int tx = threadIdx.x & 31;
        int ty = threadIdx.x >> 5;      // 0..7
        #pragma unroll
        for (int i = 0; i < 4; i++) {
            int p = p0 + ty + i * 8;
            int k = k0 + tx;
            float v = 0.0f;
            if (k < KK) {
                v = -2.0f * proto[p * KK + k];
            } else if (k < KREAL) {
                int t = k - KK;
                float s = 0.0f;
                #pragma unroll
                for (int c = 0; c < CC; c++) {
                    float q = proto[p * KK + t * CC + c];
                    s += q * q;
                }
                v = s;
            }
            tile[ty + i * 8][tx] = v;   // tile[p_local][k_local]
        }
        __syncthreads();
        #pragma unroll
        for (int i = 0; i < 4; i++) {
            int k = k0 + ty + i * 8;
            g_Wt[k * PP + p0 + tx] = tile[tx][ty + i * 8];
        }
        return;
    }
    // ---- flat copies: 8 independent float4 per thread, one pass -----------
    const float4* xs = reinterpret_cast<const float4*>(x);
    const float4* ms = reinterpret_cast<const float4*>(mask);
    float4* dx = reinterpret_cast<float4*>(out + O_INSEQ);
    float4* dm = reinterpret_cast<float4*>(out + O_MASK);
    int base = (blockIdx.x - NW_BLK) * 256 + threadIdx.x;
    #pragma unroll
    for (int j = 0; j < 8; j++) {
        int i = base + j * CSTRIDE;
        if (i < FLAT_TOT) {
            if (i < FLAT_X4) dx[i] = xs[i];
            else             dm[i - FLAT_X4] = ms[i - FLAT_X4];
        }
    }
}

// ---------------- fused GEMM (R3 inner loop, 32-deep chunks, 512 blocks) ----
// A[b,k] = mask[b,k/10]*x[b,k] (k<KK); mask[b,k-KK] (KK<=k<KREAL); 0
// part[ks][b][p] = sum over 32-deep chunk; x2p[b][ks] = sum A^2 (k<KK).
// BM=128, BN=64, 256 threads, 4b x 8p f32x2 register tile, 3 blocks/SM.
__global__ void __launch_bounds__(256, 3) k_gemm(const float* __restrict__ x,
                                                 const float* __restrict__ mask) {
    __shared__ float As[128][33];   // [b_local][k_local]  16.9 KB
    __shared__ float Ws[32][64];    // [k_local][p]         8.2 KB
    int ks = blockIdx.x;            // 0..127
    int k0 = ks * 32;
    int b0 = blockIdx.y * 128;
    int tid = threadIdx.x;
    int tb = tid & 31;              // b = b0 + tb + 32j
    int tp = tid >> 5;              // p = tp*8 + i

    // stage W chunk: 32x64 = 512 float4 / 256 threads = 2 each
    #pragma unroll
    for (int i = 0; i < 2; i++) {
        int e = tid + i * 256;
        int row = e >> 4;
        int c4 = e & 15;
        float4 v = *reinterpret_cast<const float4*>(&g_Wt[(k0 + row) * PP + c4 * 4]);
        *reinterpret_cast<float4*>(&Ws[row][c4 * 4]) = v;
    }

    unsigned long long acc2[4][4];
    #pragma unroll
    for (int j = 0; j < 4; j++)
        #pragma unroll
        for (int i = 0; i < 4; i++) acc2[j][i] = 0ull;
    float x2a[4] = {0.f, 0.f, 0.f, 0.f};

    int kloc = tid & 31;            // staging: k within chunk
    int brow0 = tid >> 5;           // staging: b row base (0..7)
    {
        int k = k0 + kloc;
        bool isx = (k < KK);
        bool ism = (!isx) && (k < KREAL);
        int t = isx ? (k / CC) : (k - KK);
        #pragma unroll
        for (int i = 0; i < 16; i++) {
            int brow = brow0 + i * 8;
            int b = b0 + brow;
            float v = 0.0f;
            if (isx)      v = x[b * KK + k] * __ldg(&mask[b * TT + t]);
            else if (ism) v = __ldg(&mask[b * TT + t]);
            As[brow][kloc] = v;
        }
    }
    __syncthreads();

    #pragma unroll 8
    for (int kk = 0; kk < 32; kk++) {
        float a[4];
        #pragma unroll
        for (int j = 0; j < 4; j++) a[j] = As[tb + 32 * j][kk];
        const unsigned long long* wp =
            reinterpret_cast<const unsigned long long*>(&Ws[kk][tp * 8]);
        unsigned long long w0 = wp[0], w1 = wp[1], w2 = wp[2], w3 = wp[3];
        #pragma unroll
        for (int j = 0; j < 4; j++) {
            unsigned long long aj = pack2(a[j]);
            fma2(acc2[j][0], aj, w0);
            fma2(acc2[j][1], aj, w1);
            fma2(acc2[j][2], aj, w2);
            fma2(acc2[j][3], aj, w3);
        }
        if (tp == 0 && (k0 + kk) < KK) {
            #pragma unroll
            for (int j = 0; j < 4; j++) x2a[j] += a[j] * a[j];
        }
    }

    // write partials
    #pragma unroll
    for (int j = 0; j < 4; j++) {
        int b = b0 + tb + 32 * j;
        float2 p0v = *reinterpret_cast<float2*>(&acc2[j][0]);
        float2 p1v = *reinterpret_cast<float2*>(&acc2[j][1]);
        float2 p2v = *reinterpret_cast<float2*>(&acc2[j][2]);
        float2 p3v = *reinterpret_cast<float2*>(&acc2[j][3]);
        float* dst = &g_part[(ks * BB + b) * PP + tp * 8];
        *reinterpret_cast<float4*>(dst)     = make_float4(p0v.x, p0v.y, p1v.x, p1v.y);
        *reinterpret_cast<float4*>(dst + 4) = make_float4(p2v.x, p2v.y, p3v.x, p3v.y);
    }
    if (tp == 0) {
        #pragma unroll
        for (int j = 0; j < 4; j++)
            g_x2p[(b0 + tb + 32 * j) * NKS + ks] = x2a[j];
    }
}

// ---------------- reduce + argmin + dist/idx/label + gather ----------------
__global__ void __launch_bounds__(256) k_reduce(const int* __restrict__ label,
                                                const float* __restrict__ proto,
                                                float* __restrict__ out) {
    __shared__ float sp[4][64];
    __shared__ float sxp[4];
    __shared__ float sv[64];
    __shared__ int si[64];
    __shared__ int sidx;
    int b = blockIdx.x;
    int tid = threadIdx.x;
    int pp = tid & 63;
    int g = tid >> 6;                  // 0..3: each sums 32 ks chunks

    float acc = 0.0f;
    #pragma unroll
    for (int i = 0; i < 32; i++)
        acc += g_part[((g * 32 + i) * BB + b) * PP + pp];
    sp[g][pp] = acc;

    if (tid < 128) {                   // x2 = sum of 128 chunk partials
        float v = g_x2p[b * NKS + tid];
        #pragma unroll
        for (int s = 16; s > 0; s >>= 1)
            v += __shfl_xor_sync(0xffffffff, v, s);
        if ((tid & 31) == 0) sxp[tid >> 5] = v;
    }
    __syncthreads();

    if (tid < 64) {
        float tot = sp[0][pp] + sp[1][pp] + sp[2][pp] + sp[3][pp]
                  + sxp[0] + sxp[1] + sxp[2] + sxp[3];
        out[O_DIST + b * PP + pp] = tot;
        sv[pp] = tot;
        si[pp] = pp;
    }
    __syncthreads();
    for (int s = 32; s > 0; s >>= 1) {
        if (tid < s) {
            float ov = sv[tid + s];
            int oi = si[tid + s];
            if (ov < sv[tid] || (ov == sv[tid] && oi < si[tid])) {
                sv[tid] = ov;
                si[tid] = oi;
            }
        }
        __syncthreads();
    }
    if (tid == 0) {
        sidx = si[0];
        out[O_IDX + b] = (float)si[0];
        out[O_LABEL + b] = (float)label[b];
    }
    __syncthreads();

    // gather selected prototype row (8B-aligned rows -> float2)
    int idx = sidx;
    const float2* src = reinterpret_cast<const float2*>(proto + idx * KK);
    float2* d0 = reinterpret_cast<float2*>(out + O_OUTSEQ + b * KK);
    #pragma unroll 4
    for (int i = tid; i < KK / 2; i += 256)
        d0[i] = src[i];
}

// ---------------- launcher --------------------------------------------------
extern "C" void kernel_launch(void* const* d_in, const int* in_sizes, int n_in,
                              void* d_out, int out_size) {
    const float* x     = (const float*)d_in[0];  // [B,T,C]
    const float* mask  = (const float*)d_in[1];  // [B,T]
    const int*   label = (const int*)d_in[2];    // [B]
    const float* proto = (const float*)d_in[3];  // [P,T,C]
    float* out = (float*)d_out;

    k_prep<<<NW_BLK + NC_BLK, 256>>>(x, mask, proto, out);
    k_gemm<<<dim3(NKS, 4), 256>>>(x, mask);
    k_reduce<<<BB, 256>>>(label, proto, out);
}

// round 12
// speedup vs baseline: 1.1606x; 1.1606x over previous
#include <cuda_runtime.h>
#include <cuda_bf16.h>
#include <cstdint>

// Problem constants
#define BB 512      // batch
#define TT 365      // time steps
#define CC 10       // channels
#define PP 64       // prototypes
#define KK 3650     // T*C
#define KREAL 4015  // 3650 + 365
#define KPAD 4096
#define NKS 64      // K-split chunks (64 deep each)

// Output layout (float32, concatenated in reference return order)
#define O_OUTSEQ 0
#define O_INSEQ  1868800
#define O_DIST   3737600
#define O_IDX    3770368
#define O_LABEL  3770880
#define O_MASK   3771392

// ---------------- scratch (device globals; no allocation allowed) ----------
__device__ float g_Wt[KPAD * PP];           // W^T, k-major: [k][p]  (1 MB)
__device__ float g_part[NKS * BB * PP];     // [ks][b][p] (8 MB)
__device__ float g_x2p[BB * NKS];           // x2 partials [b][ks]

// ---------------- packed f32x2 helpers -------------------------------------
__device__ __forceinline__ void fma2(unsigned long long& d,
                                     unsigned long long a,
                                     unsigned long long b) {
    asm("fma.rn.f32x2 %0, %1, %2, %0;" : "+l"(d) : "l"(a), "l"(b));
}
__device__ __forceinline__ unsigned long long pack2(float x) {
    unsigned long long r;
    asm("mov.b64 %0, {%1, %1};" : "=l"(r) : "f"(x));
    return r;
}

// ---------------- buildW (balanced) -----------------------------------------
// blocks [0, 230): 32x32 transpose tiles covering k<KK only
//   (115 k-tiles x 2 p-tiles; tile 114 partially guarded)
// blocks [230, 342): flat work: p^2 tail (one (p,t) sum per thread, t-fast)
//   then zero-fill k in [KREAL, KPAD)
#define NT_KT   115                    // ceil(KK/32)
#define NT_BLK  (NT_KT * 2)            // 230
#define N_P2    (TT * PP)              // 23360
#define N_ZERO  ((KPAD - KREAL) * PP)  // 5184
#define NF_BLK  112                    // ceil((N_P2 + N_ZERO)/256)

__global__ void __launch_bounds__(256) k_buildW(const float* __restrict__ proto) {
    if (blockIdx.x < NT_BLK) {
        __shared__ float tile[32][33];
        int kt = blockIdx.x % NT_KT;
        int pt = blockIdx.x / NT_KT;
        int k0 = kt * 32;
        int p0 = pt * 32;
        int tx = threadIdx.x & 31;
        int ty = threadIdx.x >> 5;      // 0..7
        #pragma unroll
        for (int i = 0; i < 4; i++) {
            int p = p0 + ty + i * 8;
            int k = k0 + tx;
            float v = 0.0f;
            if (k < KK) v = -2.0f * proto[p * KK + k];
            tile[ty + i * 8][tx] = v;   // tile[p_local][k_local]
        }
        __syncthreads();
        #pragma unroll
        for (int i = 0; i < 4; i++) {
            int k = k0 + ty + i * 8;
            if (k < KK)
                g_Wt[k * PP + p0 + tx] = tile[tx][ty + i * 8];
        }
        return;
    }
    // ---- flat: p^2 tail + zero fill ---------------------------------------
    int idx = (blockIdx.x - NT_BLK) * 256 + threadIdx.x;
    if (idx < N_P2) {
        int p = idx / TT;               // slow: same p across a warp mostly
        int t = idx % TT;               // fast: consecutive t per lane
        const float2* pb = reinterpret_cast<const float2*>(proto + p * KK + t * CC);
        float s = 0.0f;
        #pragma unroll
        for (int c = 0; c < 5; c++) {
            float2 q = pb[c];
            s += q.x * q.x + q.y * q.y;
        }
        g_Wt[(KK + t) * PP + p] = s;
    } else if (idx < N_P2 + N_ZERO) {
        g_Wt[KREAL * PP + (idx - N_P2)] = 0.0f;
    }
}

// ---------------- fused GEMM (R9-proven, untouched) -------------------------
// A[b,k] = mask[b,k/10]*x[b,k] (k<KK); mask[b,k-KK] (KK<=k<KREAL); 0
// part[ks][b][p] = sum over 64-deep chunk; x2p[b][ks] = sum A^2 (k<KK).
// BM=128, BN=64, 2 halves of 32, 256 threads, 4b x 8p f32x2 register tile.
__global__ void __launch_bounds__(256, 3) k_gemm(const float* __restrict__ x,
                                                 const float* __restrict__ mask) {
    __shared__ float As[128][33];   // [b_local][k_local]  16.9 KB
    __shared__ float Ws[64][64];    // [k_local][p]        16 KB
    int ks = blockIdx.x;            // 0..63
    int k0 = ks * 64;
    int b0 = blockIdx.y * 128;
    int tid = threadIdx.x;
    int tb = tid & 31;              // b = b0 + tb + 32j
    int tp = tid >> 5;              // p = tp*8 + i

    // stage W^T chunk: 64x64 floats = 1024 float4 / 256 threads = 4 each
    #pragma unroll
    for (int i = 0; i < 4; i++) {
        int e = tid + i * 256;
        int row = e >> 4;
        int c4 = e & 15;
        float4 v = *reinterpret_cast<const float4*>(&g_Wt[(k0 + row) * PP + c4 * 4]);
        *reinterpret_cast<float4*>(&Ws[row][c4 * 4]) = v;
    }

    unsigned long long acc2[4][4];
    #pragma unroll
    for (int j = 0; j < 4; j++)
        #pragma unroll
        for (int i = 0; i < 4; i++) acc2[j][i] = 0ull;
    float x2a[4] = {0.f, 0.f, 0.f, 0.f};

    int kloc = tid & 31;            // staging role: k within half
    int brow0 = tid >> 5;           // staging role: b row base (0..7)

    for (int h = 0; h < 2; h++) {
        int kh = k0 + h * 32;
        int k = kh + kloc;
        bool isx = (k < KK);
        bool ism = (!isx) && (k < KREAL);
        int t = isx ? (k / CC) : (k - KK);
        if (h) __syncthreads();     // protect As reuse
        // stage A half: 128 rows x 32 cols
        #pragma unroll
        for (int i = 0; i < 16; i++) {
            int brow = brow0 + i * 8;
            int b = b0 + brow;
            float v = 0.0f;
            if (isx)      v = x[b * KK + k] * __ldg(&mask[b * TT + t]);
            else if (ism) v = __ldg(&mask[b * TT + t]);
            As[brow][kloc] = v;
        }
        __syncthreads();

        #pragma unroll 8
        for (int kk = 0; kk < 32; kk++) {
            float a[4];
            #pragma unroll
            for (int j = 0; j < 4; j++) a[j] = As[tb + 32 * j][kk];
            const unsigned long long* wp =
                reinterpret_cast<const unsigned long long*>(&Ws[h * 32 + kk][tp * 8]);
            unsigned long long w0 = wp[0], w1 = wp[1], w2 = wp[2], w3 = wp[3];
            #pragma unroll
            for (int j = 0; j < 4; j++) {
                unsigned long long aj = pack2(a[j]);
                fma2(acc2[j][0], aj, w0);
                fma2(acc2[j][1], aj, w1);
                fma2(acc2[j][2], aj, w2);
                fma2(acc2[j][3], aj, w3);
            }
            if (tp == 0 && (kh + kk) < KK) {
                #pragma unroll
                for (int j = 0; j < 4; j++) x2a[j] += a[j] * a[j];
            }
        }
    }

    // write partials
    #pragma unroll
    for (int j = 0; j < 4; j++) {
        int b = b0 + tb + 32 * j;
        float2 p0v = *reinterpret_cast<float2*>(&acc2[j][0]);
        float2 p1v = *reinterpret_cast<float2*>(&acc2[j][1]);
        float2 p2v = *reinterpret_cast<float2*>(&acc2[j][2]);
        float2 p3v = *reinterpret_cast<float2*>(&acc2[j][3]);
        float* dst = &g_part[(ks * BB + b) * PP + tp * 8];
        *reinterpret_cast<float4*>(dst)     = make_float4(p0v.x, p0v.y, p1v.x, p1v.y);
        *reinterpret_cast<float4*>(dst + 4) = make_float4(p2v.x, p2v.y, p3v.x, p3v.y);
    }
    if (tp == 0) {
        #pragma unroll
        for (int j = 0; j < 4; j++)
            g_x2p[(b0 + tb + 32 * j) * NKS + ks] = x2a[j];
    }
}

// ---------------- final: reduce/argmin/gather + pass-through copies --------
// blocks [0, 512): per-b reduce + argmin + dist/idx/label + gather proto row
// blocks [512, 960): flat float4 grid-stride copies (R9-proven loop)
#define FLAT_X4   467200               // BB*KK/4
#define FLAT_M4   46720                // BB*TT/4
#define FLAT_TOT  (FLAT_X4 + FLAT_M4)
#define NC_BLK    448

__global__ void __launch_bounds__(256) k_final(const float* __restrict__ x,
                                               const float* __restrict__ mask,
                                               const int* __restrict__ label,
                                               const float* __restrict__ proto,
                                               float* __restrict__ out) {
    int tid = threadIdx.x;
    if (blockIdx.x >= BB) {
        // ---- flat copies --------------------------------------------------
        const float4* xs = reinterpret_cast<const float4*>(x);
        const float4* ms = reinterpret_cast<const float4*>(mask);
        float4* dx = reinterpret_cast<float4*>(out + O_INSEQ);
        float4* dm = reinterpret_cast<float4*>(out + O_MASK);
        int stride = NC_BLK * 256;
        for (int i = (blockIdx.x - BB) * 256 + tid; i < FLAT_TOT; i += stride) {
            if (i < FLAT_X4) dx[i] = xs[i];
            else             dm[i - FLAT_X4] = ms[i - FLAT_X4];
        }
        return;
    }

    __shared__ float sp[4][64];
    __shared__ float sx0;
    __shared__ float sv[64];
    __shared__ int si[64];
    __shared__ int sidx;
    int b = blockIdx.x;
    int pp = tid & 63;
    int g = tid >> 6;                  // 0..3: each sums 16 ks chunks

    float acc = 0.0f;
    #pragma unroll
    for (int i = 0; i < 16; i++)
        acc += g_part[((g * 16 + i) * BB + b) * PP + pp];
    sp[g][pp] = acc;

    if (tid < 32) {                    // x2 = sum of 64 chunk partials
        float v = g_x2p[b * NKS + tid] + g_x2p[b * NKS + 32 + tid];
        #pragma unroll
        for (int s = 16; s > 0; s >>= 1)
            v += __shfl_xor_sync(0xffffffff, v, s);
        if (tid == 0) sx0 = v;
    }
    __syncthreads();

    if (tid < 64) {
        float tot = sp[0][pp] + sp[1][pp] + sp[2][pp] + sp[3][pp] + sx0;
        out[O_DIST + b * PP + pp] = tot;
        sv[pp] = tot;
        si[pp] = pp;
    }
    __syncthreads();
    for (int s = 32; s > 0; s >>= 1) {
        if (tid < s) {
            float ov = sv[tid + s];
            int oi = si[tid + s];
            if (ov < sv[tid] || (ov == sv[tid] && oi < si[tid])) {
                sv[tid] = ov;
                si[tid] = oi;
            }
        }
        __syncthreads();
    }
    if (tid == 0) {
        sidx = si[0];
        out[O_IDX + b] = (float)si[0];
        out[O_LABEL + b] = (float)label[b];
    }
    __syncthreads();

    // gather selected prototype row (8B-aligned rows -> float2)
    int idx = sidx;
    const float2* src = reinterpret_cast<const float2*>(proto + idx * KK);
    float2* d0 = reinterpret_cast<float2*>(out + O_OUTSEQ + b * KK);
    #pragma unroll 4
    for (int i = tid; i < KK / 2; i += 256)
        d0[i] = src[i];
}

// ---------------- launcher --------------------------------------------------
extern "C" void kernel_launch(void* const* d_in, const int* in_sizes, int n_in,
                              void* d_out, int out_size) {
    const float* x     = (const float*)d_in[0];  // [B,T,C]
    const float* mask  = (const float*)d_in[1];  // [B,T]
    const int*   label = (const int*)d_in[2];    // [B]
    const float* proto = (const float*)d_in[3];  // [P,T,C]
    float* out = (float*)d_out;

    k_buildW<<<NT_BLK + NF_BLK, 256>>>(proto);
    k_gemm<<<dim3(NKS, 4), 256>>>(x, mask);
    k_final<<<BB + NC_BLK, 256>>>(x, mask, label, proto, out);
}